// round 1
// baseline (speedup 1.0000x reference)
#include <cuda_runtime.h>
#include <math.h>

#define Hn   1024
#define Ln   8192
#define Bn   4
#define KDn  64
#define FLEN 512

// scratch: filters + post-gelu activations
__device__ float g_filt[Hn * FLEN];
__device__ float g_g[(size_t)Bn * Hn * Ln];

// ---------------------------------------------------------------------------
// Kernel A: build the 512-tap filter per head, L2-normalize.
// grid = (Hn), block = (512); thread t computes tap t.
// ---------------------------------------------------------------------------
__global__ void build_filter_kernel(const float* __restrict__ k0,
                                    const float* __restrict__ k1,
                                    const float* __restrict__ k2,
                                    const float* __restrict__ k3) {
    const int h = blockIdx.x;
    const int t = threadIdx.x;  // 0..511

    float v = 0.0f;
    // i = 0: length 64, no interpolation, weight 2^(NS-1) = 8
    if (t < 64) v += 8.0f * k0[h * KDn + t];

    // i = 1..3: linear interpolation (align_corners=False), weight 8 >> i
    const float* ks[3] = {k1, k2, k3};
    #pragma unroll
    for (int i = 1; i < 4; i++) {
        const int len = KDn << i;
        if (t < len) {
            const float scale = (float)(1 << i);
            float coord = ((float)t + 0.5f) / scale - 0.5f;
            coord = fminf(fmaxf(coord, 0.0f), 63.0f);
            int lo = (int)floorf(coord);
            if (lo > 63) lo = 63;
            int hi = lo + 1; if (hi > 63) hi = 63;
            const float w = coord - (float)lo;
            const float* kk = ks[i - 1];
            const float val = kk[h * KDn + lo] * (1.0f - w) + kk[h * KDn + hi] * w;
            v += val * (float)(1 << (3 - i));
        }
    }

    __shared__ float red[512];
    red[t] = v * v;
    __syncthreads();
    for (int s = 256; s > 0; s >>= 1) {
        if (t < s) red[t] += red[t + s];
        __syncthreads();
    }
    const float norm = sqrtf(red[0]);
    g_filt[h * FLEN + t] = v / norm;
}

// ---------------------------------------------------------------------------
// Kernel B: causal 512-tap FIR + D*u + exact GELU -> g_g
// grid = (Ln/2048, Hn, Bn), block = 256 threads, 8 contiguous outputs/thread.
// Register window of 16 u-values per 8-tap chunk; all smem loads are LDS.128
// (4 conflict-free phases), filter loads are broadcast.
// ---------------------------------------------------------------------------
__global__ void __launch_bounds__(256) fir_gelu_kernel(const float* __restrict__ u,
                                                       const float* __restrict__ D) {
    const int chunk = blockIdx.x;   // 0..3
    const int h     = blockIdx.y;
    const int b     = blockIdx.z;
    const int tid   = threadIdx.x;  // 0..255

    __shared__ __align__(16) float s_u[FLEN + 2048];  // 512 history + 2048 tile
    __shared__ __align__(16) float s_f[FLEN];

    const int l0 = chunk * 2048;
    const float* up = u + ((size_t)(b * Hn + h)) * Ln;

    for (int i = tid; i < FLEN + 2048; i += 256) {
        const int gl = l0 - FLEN + i;
        s_u[i] = (gl >= 0) ? up[gl] : 0.0f;
    }
    for (int i = tid; i < FLEN; i += 256) s_f[i] = g_filt[h * FLEN + i];
    __syncthreads();

    float acc[8] = {0.f,0.f,0.f,0.f,0.f,0.f,0.f,0.f};
    const int base = FLEN + tid * 8;

    for (int t0 = 0; t0 < FLEN; t0 += 8) {
        const float4 fA = *(const float4*)&s_f[t0];
        const float4 fB = *(const float4*)&s_f[t0 + 4];
        float x[16];
        #pragma unroll
        for (int k4 = 0; k4 < 4; k4++)
            *(float4*)&x[k4 * 4] = *(const float4*)&s_u[base - t0 - 8 + k4 * 4];
        #pragma unroll
        for (int r = 0; r < 8; r++) {
            // tap t0+d multiplies u[l - t0 - d] = x[8 + r - d]
            acc[r] += fA.x * x[8 + r];
            acc[r] += fA.y * x[7 + r];
            acc[r] += fA.z * x[6 + r];
            acc[r] += fA.w * x[5 + r];
            acc[r] += fB.x * x[4 + r];
            acc[r] += fB.y * x[3 + r];
            acc[r] += fB.z * x[2 + r];
            acc[r] += fB.w * x[1 + r];
        }
    }

    const float d = D[h];
    float res[8];
    #pragma unroll
    for (int r = 0; r < 8; r++) {
        const float v = acc[r] + d * s_u[base + r];
        res[r] = 0.5f * v * (1.0f + erff(v * 0.70710678118654752f));
    }

    float* gp = g_g + ((size_t)(b * Hn + h)) * Ln + l0 + tid * 8;
    *(float4*)&gp[0] = make_float4(res[0], res[1], res[2], res[3]);
    *(float4*)&gp[4] = make_float4(res[4], res[5], res[6], res[7]);
}

// ---------------------------------------------------------------------------
// Kernel C: SGEMM  out[b,o,l] = sum_h W[o,h] * g_g[b,h,l] + bias[o]
// A = W (1024x1024 row-major), B = g_g[b] (1024 x 8192), C = out[b].
// 128x128 block tile, BK=16, 256 threads, 8x8 microtile.
// grid = (Ln/128, Hn/128, Bn)
// ---------------------------------------------------------------------------
#define BM 128
#define BN 128
#define BK 16

__global__ void __launch_bounds__(256) gemm_kernel(const float* __restrict__ Wm,
                                                   const float* __restrict__ bias,
                                                   float* __restrict__ out) {
    const int b  = blockIdx.z;
    const int m0 = blockIdx.y * BM;
    const int n0 = blockIdx.x * BN;
    const int tid = threadIdx.x;
    const int tx = tid % 16;     // n direction
    const int ty = tid / 16;     // m direction

    const float* Bmat = g_g + (size_t)b * Hn * Ln;

    __shared__ __align__(16) float As[BK][BM];
    __shared__ __align__(16) float Bs[BK][BN];

    float acc[8][8];
    #pragma unroll
    for (int i = 0; i < 8; i++)
        #pragma unroll
        for (int j = 0; j < 8; j++) acc[i][j] = 0.0f;

    for (int k0 = 0; k0 < Hn; k0 += BK) {
        // A tile: 128 rows x 16 cols, transposed into As[k][m]
        {
            const int r  = tid >> 1;          // 0..127
            const int c8 = (tid & 1) * 8;     // 0 or 8
            const float4 a0 = *(const float4*)&Wm[(size_t)(m0 + r) * Hn + k0 + c8];
            const float4 a1 = *(const float4*)&Wm[(size_t)(m0 + r) * Hn + k0 + c8 + 4];
            As[c8 + 0][r] = a0.x; As[c8 + 1][r] = a0.y;
            As[c8 + 2][r] = a0.z; As[c8 + 3][r] = a0.w;
            As[c8 + 4][r] = a1.x; As[c8 + 5][r] = a1.y;
            As[c8 + 6][r] = a1.z; As[c8 + 7][r] = a1.w;
        }
        // B tile: 16 rows x 128 cols
        {
            const int r = tid >> 5;           // 0..7
            const int c = (tid & 31) * 4;     // 0..124
            const float4 b0 = *(const float4*)&Bmat[(size_t)(k0 + r) * Ln + n0 + c];
            const float4 b1 = *(const float4*)&Bmat[(size_t)(k0 + r + 8) * Ln + n0 + c];
            *(float4*)&Bs[r][c]     = b0;
            *(float4*)&Bs[r + 8][c] = b1;
        }
        __syncthreads();

        #pragma unroll
        for (int kk = 0; kk < BK; kk++) {
            float ra[8], rb[8];
            *(float4*)&ra[0] = *(const float4*)&As[kk][ty * 8];
            *(float4*)&ra[4] = *(const float4*)&As[kk][ty * 8 + 4];
            *(float4*)&rb[0] = *(const float4*)&Bs[kk][tx * 8];
            *(float4*)&rb[4] = *(const float4*)&Bs[kk][tx * 8 + 4];
            #pragma unroll
            for (int i = 0; i < 8; i++)
                #pragma unroll
                for (int j = 0; j < 8; j++)
                    acc[i][j] += ra[i] * rb[j];
        }
        __syncthreads();
    }

    #pragma unroll
    for (int i = 0; i < 8; i++) {
        const int o = m0 + ty * 8 + i;
        const float bv = bias[o];
        float* op = out + ((size_t)b * Hn + o) * Ln + n0 + tx * 8;
        *(float4*)&op[0] = make_float4(acc[i][0] + bv, acc[i][1] + bv,
                                       acc[i][2] + bv, acc[i][3] + bv);
        *(float4*)&op[4] = make_float4(acc[i][4] + bv, acc[i][5] + bv,
                                       acc[i][6] + bv, acc[i][7] + bv);
    }
}

// ---------------------------------------------------------------------------
extern "C" void kernel_launch(void* const* d_in, const int* in_sizes, int n_in,
                              void* d_out, int out_size) {
    const float* u    = (const float*)d_in[0];
    const float* k0   = (const float*)d_in[1];
    const float* k1   = (const float*)d_in[2];
    const float* k2   = (const float*)d_in[3];
    const float* k3   = (const float*)d_in[4];
    const float* D    = (const float*)d_in[5];
    const float* Wm   = (const float*)d_in[6];
    const float* bias = (const float*)d_in[7];
    float* out = (float*)d_out;

    build_filter_kernel<<<Hn, 512>>>(k0, k1, k2, k3);

    dim3 gconv(Ln / 2048, Hn, Bn);
    fir_gelu_kernel<<<gconv, 256>>>(u, D);

    dim3 ggemm(Ln / BN, Hn / BM, Bn);
    gemm_kernel<<<ggemm, 256>>>(Wm, bias, out);
}

// round 4
// speedup vs baseline: 1.4362x; 1.4362x over previous
#include <cuda_runtime.h>
#include <cuda_bf16.h>
#include <math.h>
#include <stdint.h>

#define Hn   1024
#define Ln   8192
#define Bn   4
#define KDn  64
#define FLEN 512

// ---------------------------------------------------------------------------
// device scratch
// ---------------------------------------------------------------------------
__device__ float g_filt[Hn * FLEN];
__device__ float g_g[(size_t)Bn * Hn * Ln];                 // post-gelu fp32
__device__ __nv_bfloat16 g_Whi[Hn * Hn];
__device__ __nv_bfloat16 g_Wlo[Hn * Hn];
__device__ __nv_bfloat16 g_thi[(size_t)Bn * Ln * Hn];       // g transposed, hi
__device__ __nv_bfloat16 g_tlo[(size_t)Bn * Ln * Hn];       // g transposed, lo

// ---------------------------------------------------------------------------
// helpers
// ---------------------------------------------------------------------------
__device__ __forceinline__ uint32_t smem_u32(const void* p) {
    uint32_t a;
    asm("{ .reg .u64 t; cvta.to.shared.u64 t, %1; cvt.u32.u64 %0, t; }"
        : "=r"(a) : "l"(p));
    return a;
}
__device__ __forceinline__ void cp16(uint32_t dst, const void* src) {
    asm volatile("cp.async.cg.shared.global [%0], [%1], 16;" :: "r"(dst), "l"(src));
}
#define CP_COMMIT() asm volatile("cp.async.commit_group;" ::: "memory")

__device__ __forceinline__ void ldsm4(uint32_t* r, uint32_t addr) {
    asm volatile("ldmatrix.sync.aligned.m8n8.x4.shared.b16 {%0,%1,%2,%3}, [%4];"
                 : "=r"(r[0]), "=r"(r[1]), "=r"(r[2]), "=r"(r[3]) : "r"(addr));
}
__device__ __forceinline__ void mma16816(float* c, const uint32_t* a, const uint32_t* b) {
    asm volatile("mma.sync.aligned.m16n8k16.row.col.f32.bf16.bf16.f32 "
                 "{%0,%1,%2,%3}, {%4,%5,%6,%7}, {%8,%9}, {%0,%1,%2,%3};"
                 : "+f"(c[0]), "+f"(c[1]), "+f"(c[2]), "+f"(c[3])
                 : "r"(a[0]), "r"(a[1]), "r"(a[2]), "r"(a[3]), "r"(b[0]), "r"(b[1]));
}

// ---------------------------------------------------------------------------
// Kernel A: build the 512-tap filter per head, L2-normalize.
// ---------------------------------------------------------------------------
__global__ void build_filter_kernel(const float* __restrict__ k0,
                                    const float* __restrict__ k1,
                                    const float* __restrict__ k2,
                                    const float* __restrict__ k3) {
    const int h = blockIdx.x;
    const int t = threadIdx.x;  // 0..511

    float v = 0.0f;
    if (t < 64) v += 8.0f * k0[h * KDn + t];
    const float* ks[3] = {k1, k2, k3};
    #pragma unroll
    for (int i = 1; i < 4; i++) {
        const int len = KDn << i;
        if (t < len) {
            const float scale = (float)(1 << i);
            float coord = ((float)t + 0.5f) / scale - 0.5f;
            coord = fminf(fmaxf(coord, 0.0f), 63.0f);
            int lo = (int)floorf(coord);
            if (lo > 63) lo = 63;
            int hi = lo + 1; if (hi > 63) hi = 63;
            const float w = coord - (float)lo;
            const float* kk = ks[i - 1];
            const float val = kk[h * KDn + lo] * (1.0f - w) + kk[h * KDn + hi] * w;
            v += val * (float)(1 << (3 - i));
        }
    }
    __shared__ float red[512];
    red[t] = v * v;
    __syncthreads();
    for (int s = 256; s > 0; s >>= 1) {
        if (t < s) red[t] += red[t + s];
        __syncthreads();
    }
    g_filt[h * FLEN + t] = v / sqrtf(red[0]);
}

// ---------------------------------------------------------------------------
// Kernel B: causal 512-tap FIR + D*u + exact GELU -> g_g (fp32)
// ---------------------------------------------------------------------------
__global__ void __launch_bounds__(256) fir_gelu_kernel(const float* __restrict__ u,
                                                       const float* __restrict__ D) {
    const int chunk = blockIdx.x;
    const int h     = blockIdx.y;
    const int b     = blockIdx.z;
    const int tid   = threadIdx.x;

    __shared__ __align__(16) float s_u[FLEN + 2048];
    __shared__ __align__(16) float s_f[FLEN];

    const int l0 = chunk * 2048;
    const float* up = u + ((size_t)(b * Hn + h)) * Ln;

    for (int i = tid; i < FLEN + 2048; i += 256) {
        const int gl = l0 - FLEN + i;
        s_u[i] = (gl >= 0) ? up[gl] : 0.0f;
    }
    for (int i = tid; i < FLEN; i += 256) s_f[i] = g_filt[h * FLEN + i];
    __syncthreads();

    float acc[8] = {0.f,0.f,0.f,0.f,0.f,0.f,0.f,0.f};
    const int base = FLEN + tid * 8;

    for (int t0 = 0; t0 < FLEN; t0 += 8) {
        const float4 fA = *(const float4*)&s_f[t0];
        const float4 fB = *(const float4*)&s_f[t0 + 4];
        float x[16];
        #pragma unroll
        for (int k4 = 0; k4 < 4; k4++)
            *(float4*)&x[k4 * 4] = *(const float4*)&s_u[base - t0 - 8 + k4 * 4];
        #pragma unroll
        for (int r = 0; r < 8; r++) {
            acc[r] += fA.x * x[8 + r];
            acc[r] += fA.y * x[7 + r];
            acc[r] += fA.z * x[6 + r];
            acc[r] += fA.w * x[5 + r];
            acc[r] += fB.x * x[4 + r];
            acc[r] += fB.y * x[3 + r];
            acc[r] += fB.z * x[2 + r];
            acc[r] += fB.w * x[1 + r];
        }
    }

    const float d = D[h];
    float res[8];
    #pragma unroll
    for (int r = 0; r < 8; r++) {
        const float v = acc[r] + d * s_u[base + r];
        res[r] = 0.5f * v * (1.0f + erff(v * 0.70710678118654752f));
    }
    float* gp = g_g + ((size_t)(b * Hn + h)) * Ln + l0 + tid * 8;
    *(float4*)&gp[0] = make_float4(res[0], res[1], res[2], res[3]);
    *(float4*)&gp[4] = make_float4(res[4], res[5], res[6], res[7]);
}

// ---------------------------------------------------------------------------
// Kernel W: split W into bf16 hi/lo
// ---------------------------------------------------------------------------
__global__ void wsplit_kernel(const float* __restrict__ W) {
    const int i = blockIdx.x * 256 + threadIdx.x;
    const float x = W[i];
    const __nv_bfloat16 h = __float2bfloat16(x);
    g_Whi[i] = h;
    g_Wlo[i] = __float2bfloat16(x - __bfloat162float(h));
}

// ---------------------------------------------------------------------------
// Kernel T: transpose g[b,h,l] -> g_t[b,l,h] with bf16 hi/lo split
// ---------------------------------------------------------------------------
__global__ void __launch_bounds__(256) tsplit_kernel() {
    __shared__ float t[64][65];
    const int l0 = blockIdx.x * 64;
    const int h0 = blockIdx.y * 64;
    const int b  = blockIdx.z;
    const int tid = threadIdx.x;

    for (int i = tid; i < 4096; i += 256) {
        const int hr = i >> 6, lc = i & 63;
        t[hr][lc] = g_g[((size_t)(b * Hn + h0 + hr)) * Ln + l0 + lc];
    }
    __syncthreads();
    for (int i = tid; i < 4096; i += 256) {
        const int hc = i & 63, lr = i >> 6;
        const float x = t[hc][lr];
        const __nv_bfloat16 hi = __float2bfloat16(x);
        const size_t o = ((size_t)(b * Ln + l0 + lr)) * Hn + h0 + hc;
        g_thi[o] = hi;
        g_tlo[o] = __float2bfloat16(x - __bfloat162float(hi));
    }
}

// ---------------------------------------------------------------------------
// Kernel C: mma.sync bf16-split GEMM
// out[b,o,l] = sum_h W[o,h] * g[b,h,l] + bias[o]
// CTA tile 128(M=o) x 128(N=l), BK=32 (K=h), double-buffered cp.async.
// 8 warps in 4x2 grid; warp tile 32x64; m16n8k16 HMMA, 3-term bf16 split.
// Smem rows padded to 40 bf16 (80B) -> conflict-free ldmatrix.
// ---------------------------------------------------------------------------
#define BK 32
#define ROWB 80                       // bytes per smem row (32 bf16 + 8 pad)
#define MATB (128 * ROWB)             // 10240 B per matrix
#define STAGEB (4 * MATB)             // aHi,aLo,bHi,bLo = 40960 B
#define GEMM_SMEM (2 * STAGEB)        // 81920 B

__global__ void __launch_bounds__(256, 1)
gemm_mma_kernel(const float* __restrict__ bias, float* __restrict__ out) {
    extern __shared__ __align__(16) char smem_raw[];
    const uint32_t buf = smem_u32(smem_raw);

    const int tid  = threadIdx.x;
    const int wid  = tid >> 5;
    const int lane = tid & 31;
    const int wm   = wid & 3;          // m sub-tile 0..3 (x32)
    const int wn   = wid >> 2;         // n sub-tile 0..1 (x64)
    const int m0   = blockIdx.x * 128;
    const int n0   = blockIdx.y * 128;
    const int b    = blockIdx.z;

    const __nv_bfloat16* Bhi = g_thi + (size_t)b * Ln * Hn;
    const __nv_bfloat16* Blo = g_tlo + (size_t)b * Ln * Hn;

    auto load_chunk = [&](int c, int s) {
        const int k0 = c * BK;
        const uint32_t sb = buf + s * STAGEB;
        #pragma unroll
        for (int j = 0; j < 2; j++) {
            const int i   = tid + j * 256;      // 0..511
            const int row = i >> 2;
            const int cc  = i & 3;              // 8-elem chunk
            const uint32_t so = row * ROWB + cc * 16;
            const size_t ga = (size_t)(m0 + row) * Hn + k0 + cc * 8;
            const size_t gb = (size_t)(n0 + row) * Hn + k0 + cc * 8;
            cp16(sb + 0 * MATB + so, g_Whi + ga);
            cp16(sb + 1 * MATB + so, g_Wlo + ga);
            cp16(sb + 2 * MATB + so, Bhi + gb);
            cp16(sb + 3 * MATB + so, Blo + gb);
        }
        CP_COMMIT();
    };

    float acc[2][8][4];
    #pragma unroll
    for (int i = 0; i < 2; i++)
        #pragma unroll
        for (int j = 0; j < 8; j++)
            #pragma unroll
            for (int q = 0; q < 4; q++) acc[i][j][q] = 0.0f;

    load_chunk(0, 0);

    const int NCH = Hn / BK;   // 32
    for (int c = 0; c < NCH; c++) {
        const int s = c & 1;
        if (c + 1 < NCH) {
            load_chunk(c + 1, s ^ 1);
            asm volatile("cp.async.wait_group 1;" ::: "memory");
        } else {
            asm volatile("cp.async.wait_group 0;" ::: "memory");
        }
        __syncthreads();

        const uint32_t aHi = buf + s * STAGEB;
        const uint32_t aLo = aHi + MATB;
        const uint32_t bHi = aHi + 2 * MATB;
        const uint32_t bLo = aHi + 3 * MATB;

        #pragma unroll
        for (int kk = 0; kk < BK; kk += 16) {
            uint32_t ah[2][4], al[2][4], bh[4][4], bl[4][4];
            #pragma unroll
            for (int mi = 0; mi < 2; mi++) {
                const int row = wm * 32 + mi * 16 + (lane & 15);
                const uint32_t off = row * ROWB + kk * 2 + ((lane >> 4) & 1) * 16;
                ldsm4(ah[mi], aHi + off);
                ldsm4(al[mi], aLo + off);
            }
            #pragma unroll
            for (int ng = 0; ng < 4; ng++) {
                const int row = wn * 64 + ng * 16 + (lane & 7) + ((lane >> 4) & 1) * 8;
                const uint32_t off = row * ROWB + kk * 2 + ((lane >> 3) & 1) * 16;
                ldsm4(bh[ng], bHi + off);
                ldsm4(bl[ng], bLo + off);
            }
            #pragma unroll
            for (int mi = 0; mi < 2; mi++)
                #pragma unroll
                for (int ng = 0; ng < 4; ng++)
                    #pragma unroll
                    for (int hf = 0; hf < 2; hf++) {
                        float* cc = acc[mi][ng * 2 + hf];
                        mma16816(cc, ah[mi], &bh[ng][hf * 2]);
                        mma16816(cc, ah[mi], &bl[ng][hf * 2]);
                        mma16816(cc, al[mi], &bh[ng][hf * 2]);
                    }
        }
        __syncthreads();
    }

    // epilogue: d0,d1 -> row g, cols 2t,2t+1 ; d2,d3 -> row g+8
    const int g  = lane >> 2;
    const int tg = lane & 3;
    #pragma unroll
    for (int mi = 0; mi < 2; mi++) {
        const int o0 = m0 + wm * 32 + mi * 16 + g;
        const float bv0 = bias[o0];
        const float bv1 = bias[o0 + 8];
        float* r0 = out + ((size_t)(b * Hn + o0)) * Ln + n0 + wn * 64;
        float* r1 = out + ((size_t)(b * Hn + o0 + 8)) * Ln + n0 + wn * 64;
        #pragma unroll
        for (int nf = 0; nf < 8; nf++) {
            const int col = nf * 8 + tg * 2;
            *(float2*)&r0[col] = make_float2(acc[mi][nf][0] + bv0, acc[mi][nf][1] + bv0);
            *(float2*)&r1[col] = make_float2(acc[mi][nf][2] + bv1, acc[mi][nf][3] + bv1);
        }
    }
}

// ---------------------------------------------------------------------------
extern "C" void kernel_launch(void* const* d_in, const int* in_sizes, int n_in,
                              void* d_out, int out_size) {
    const float* u    = (const float*)d_in[0];
    const float* k0   = (const float*)d_in[1];
    const float* k1   = (const float*)d_in[2];
    const float* k2   = (const float*)d_in[3];
    const float* k3   = (const float*)d_in[4];
    const float* D    = (const float*)d_in[5];
    const float* Wm   = (const float*)d_in[6];
    const float* bias = (const float*)d_in[7];
    float* out = (float*)d_out;

    cudaFuncSetAttribute(gemm_mma_kernel,
                         cudaFuncAttributeMaxDynamicSharedMemorySize, GEMM_SMEM);

    build_filter_kernel<<<Hn, 512>>>(k0, k1, k2, k3);

    dim3 gconv(Ln / 2048, Hn, Bn);
    fir_gelu_kernel<<<gconv, 256>>>(u, D);

    wsplit_kernel<<<(Hn * Hn) / 256, 256>>>(Wm);

    dim3 gt(Ln / 64, Hn / 64, Bn);
    tsplit_kernel<<<gt, 256>>>();

    dim3 gg(Hn / 128, Ln / 128, Bn);   // m fastest -> B-tile L2 reuse
    gemm_mma_kernel<<<gg, 256, GEMM_SMEM>>>(bias, out);
}

// round 7
// speedup vs baseline: 1.9366x; 1.3484x over previous
#include <cuda_runtime.h>
#include <cuda_bf16.h>
#include <math.h>
#include <stdint.h>

#define Hn   1024
#define Ln   8192
#define Bn   4
#define KDn  64
#define FLEN 512

// ---------------------------------------------------------------------------
// device scratch
// ---------------------------------------------------------------------------
__device__ float g_filt[Hn * FLEN];
__device__ float g_g[(size_t)Bn * Hn * Ln];                 // post-gelu fp32
__device__ __nv_bfloat16 g_Whi[Hn * Hn];
__device__ __nv_bfloat16 g_Wlo[Hn * Hn];
__device__ __nv_bfloat16 g_thi[(size_t)Bn * Ln * Hn];       // g transposed, hi
__device__ __nv_bfloat16 g_tlo[(size_t)Bn * Ln * Hn];       // g transposed, lo

// ---------------------------------------------------------------------------
// helpers
// ---------------------------------------------------------------------------
__device__ __forceinline__ uint32_t smem_u32(const void* p) {
    uint32_t a;
    asm("{ .reg .u64 t; cvta.to.shared.u64 t, %1; cvt.u32.u64 %0, t; }"
        : "=r"(a) : "l"(p));
    return a;
}
__device__ __forceinline__ void cp16(uint32_t dst, const void* src) {
    asm volatile("cp.async.cg.shared.global [%0], [%1], 16;" :: "r"(dst), "l"(src));
}
#define CP_COMMIT() asm volatile("cp.async.commit_group;" ::: "memory")

__device__ __forceinline__ void ldsm4(uint32_t* r, uint32_t addr) {
    asm volatile("ldmatrix.sync.aligned.m8n8.x4.shared.b16 {%0,%1,%2,%3}, [%4];"
                 : "=r"(r[0]), "=r"(r[1]), "=r"(r[2]), "=r"(r[3]) : "r"(addr));
}
__device__ __forceinline__ void mma16816(float* c, const uint32_t* a, const uint32_t* b) {
    asm volatile("mma.sync.aligned.m16n8k16.row.col.f32.bf16.bf16.f32 "
                 "{%0,%1,%2,%3}, {%4,%5,%6,%7}, {%8,%9}, {%0,%1,%2,%3};"
                 : "+f"(c[0]), "+f"(c[1]), "+f"(c[2]), "+f"(c[3])
                 : "r"(a[0]), "r"(a[1]), "r"(a[2]), "r"(a[3]), "r"(b[0]), "r"(b[1]));
}

// packed f32x2 (Blackwell): one instr = 2 fp32 FMAs per lane
__device__ __forceinline__ uint64_t pack2(float lo, float hi) {
    uint64_t r;
    asm("mov.b64 %0, {%1, %2};" : "=l"(r) : "f"(lo), "f"(hi));
    return r;
}
__device__ __forceinline__ uint64_t ffma2(uint64_t a, uint64_t b, uint64_t c) {
    uint64_t r;
    asm("fma.rn.f32x2 %0, %1, %2, %3;" : "=l"(r) : "l"(a), "l"(b), "l"(c));
    return r;
}
__device__ __forceinline__ float2 unpack2(uint64_t p) {
    float2 v;
    asm("mov.b64 {%0, %1}, %2;" : "=f"(v.x), "=f"(v.y) : "l"(p));
    return v;
}

// ---------------------------------------------------------------------------
// Kernel A: build the 512-tap filter per head, L2-normalize.
// ---------------------------------------------------------------------------
__global__ void build_filter_kernel(const float* __restrict__ k0,
                                    const float* __restrict__ k1,
                                    const float* __restrict__ k2,
                                    const float* __restrict__ k3) {
    const int h = blockIdx.x;
    const int t = threadIdx.x;  // 0..511

    float v = 0.0f;
    if (t < 64) v += 8.0f * k0[h * KDn + t];
    const float* ks[3] = {k1, k2, k3};
    #pragma unroll
    for (int i = 1; i < 4; i++) {
        const int len = KDn << i;
        if (t < len) {
            const float scale = (float)(1 << i);
            float coord = ((float)t + 0.5f) / scale - 0.5f;
            coord = fminf(fmaxf(coord, 0.0f), 63.0f);
            int lo = (int)floorf(coord);
            if (lo > 63) lo = 63;
            int hi = lo + 1; if (hi > 63) hi = 63;
            const float w = coord - (float)lo;
            const float* kk = ks[i - 1];
            const float val = kk[h * KDn + lo] * (1.0f - w) + kk[h * KDn + hi] * w;
            v += val * (float)(1 << (3 - i));
        }
    }
    __shared__ float red[512];
    red[t] = v * v;
    __syncthreads();
    for (int s = 256; s > 0; s >>= 1) {
        if (t < s) red[t] += red[t + s];
        __syncthreads();
    }
    g_filt[h * FLEN + t] = v / sqrtf(red[0]);
}

// ---------------------------------------------------------------------------
// Kernel B: causal 512-tap FIR + D*u + exact GELU -> g_g (fp32)
// f32x2-packed inner loop, sliding 16-value window (two 8-float halves).
// ---------------------------------------------------------------------------
struct Half8 {
    float   x[8];
    uint64_t e[4];   // (x0,x1)(x2,x3)(x4,x5)(x6,x7)
    uint64_t o[3];   // (x1,x2)(x3,x4)(x5,x6)
};

__device__ __forceinline__ void load_half(Half8& h, const float* p) {
    *(float4*)&h.x[0] = *(const float4*)p;
    *(float4*)&h.x[4] = *(const float4*)(p + 4);
    h.e[0] = pack2(h.x[0], h.x[1]);
    h.e[1] = pack2(h.x[2], h.x[3]);
    h.e[2] = pack2(h.x[4], h.x[5]);
    h.e[3] = pack2(h.x[6], h.x[7]);
    h.o[0] = pack2(h.x[1], h.x[2]);
    h.o[1] = pack2(h.x[3], h.x[4]);
    h.o[2] = pack2(h.x[5], h.x[6]);
}

// 8 taps f[0..7] against window x[0..15] = (lo.x | hi.x):
// acc[2q]+w lanes: acc[2q] += f[d]*x[8+2q-d], acc[2q+1] += f[d]*x[9+2q-d]
__device__ __forceinline__ void fir_step(uint64_t accP[4],
                                         const Half8& lo, const Half8& hi,
                                         const float* f) {
    const uint64_t cross = pack2(lo.x[7], hi.x[0]);   // O[3] = (x7,x8)
    float4 fa = *(const float4*)&f[0];
    float4 fb = *(const float4*)&f[4];
    const float fs[8] = {fa.x, fa.y, fa.z, fa.w, fb.x, fb.y, fb.z, fb.w};
    #pragma unroll
    for (int d = 0; d < 8; d++) {
        const uint64_t fd = pack2(fs[d], fs[d]);
        #pragma unroll
        for (int q = 0; q < 4; q++) {
            const int st = 8 + 2 * q - d;             // pair start in x[]
            uint64_t xv;
            if ((d & 1) == 0) {                       // even start -> E[st/2]
                const int i = st >> 1;                // 1..7
                xv = (i < 4) ? lo.e[i] : hi.e[i - 4];
            } else {                                  // odd start -> O[(st-1)/2]
                const int j = (st - 1) >> 1;          // 0..6
                xv = (j < 3) ? lo.o[j] : (j == 3 ? cross : hi.o[j - 4]);
            }
            accP[q] = ffma2(fd, xv, accP[q]);
        }
    }
}

__global__ void __launch_bounds__(256) fir_gelu_kernel(const float* __restrict__ u,
                                                       const float* __restrict__ D) {
    const int chunk = blockIdx.x;
    const int h     = blockIdx.y;
    const int b     = blockIdx.z;
    const int tid   = threadIdx.x;

    __shared__ __align__(16) float s_u[FLEN + 2048];
    __shared__ __align__(16) float s_f[FLEN];

    const int l0 = chunk * 2048;
    const float* up = u + ((size_t)(b * Hn + h)) * Ln;

    for (int i = tid; i < FLEN + 2048; i += 256) {
        const int gl = l0 - FLEN + i;
        s_u[i] = (gl >= 0) ? up[gl] : 0.0f;
    }
    for (int i = tid; i < FLEN; i += 256) s_f[i] = g_filt[h * FLEN + i];
    __syncthreads();

    const int base = FLEN + tid * 8;

    uint64_t accP[4];
    #pragma unroll
    for (int q = 0; q < 4; q++) accP[q] = pack2(0.0f, 0.0f);

    Half8 A, B;
    load_half(B, &s_u[base]);                 // hi half for t0 = 0
    #pragma unroll 4
    for (int t0 = 0; t0 < FLEN; t0 += 16) {
        load_half(A, &s_u[base - t0 - 8]);
        fir_step(accP, A, B, &s_f[t0]);
        load_half(B, &s_u[base - t0 - 16]);
        fir_step(accP, B, A, &s_f[t0 + 8]);
    }

    const float d = D[h];
    float res[8];
    #pragma unroll
    for (int q = 0; q < 4; q++) {
        const float2 a = unpack2(accP[q]);
        const float v0 = a.x + d * s_u[base + 2 * q];
        const float v1 = a.y + d * s_u[base + 2 * q + 1];
        res[2 * q]     = 0.5f * v0 * (1.0f + erff(v0 * 0.70710678118654752f));
        res[2 * q + 1] = 0.5f * v1 * (1.0f + erff(v1 * 0.70710678118654752f));
    }
    float* gp = g_g + ((size_t)(b * Hn + h)) * Ln + l0 + tid * 8;
    *(float4*)&gp[0] = make_float4(res[0], res[1], res[2], res[3]);
    *(float4*)&gp[4] = make_float4(res[4], res[5], res[6], res[7]);
}

// ---------------------------------------------------------------------------
// Kernel W: split W into bf16 hi/lo
// ---------------------------------------------------------------------------
__global__ void wsplit_kernel(const float* __restrict__ W) {
    const int i = blockIdx.x * 256 + threadIdx.x;
    const float x = W[i];
    const __nv_bfloat16 h = __float2bfloat16(x);
    g_Whi[i] = h;
    g_Wlo[i] = __float2bfloat16(x - __bfloat162float(h));
}

// ---------------------------------------------------------------------------
// Kernel T: transpose g[b,h,l] -> g_t[b,l,h] with bf16 hi/lo split
// ---------------------------------------------------------------------------
__global__ void __launch_bounds__(256) tsplit_kernel() {
    __shared__ float t[64][65];
    const int l0 = blockIdx.x * 64;
    const int h0 = blockIdx.y * 64;
    const int b  = blockIdx.z;
    const int tid = threadIdx.x;

    for (int i = tid; i < 4096; i += 256) {
        const int hr = i >> 6, lc = i & 63;
        t[hr][lc] = g_g[((size_t)(b * Hn + h0 + hr)) * Ln + l0 + lc];
    }
    __syncthreads();
    for (int i = tid; i < 4096; i += 256) {
        const int hc = i & 63, lr = i >> 6;
        const float x = t[hc][lr];
        const __nv_bfloat16 hi = __float2bfloat16(x);
        const size_t o = ((size_t)(b * Ln + l0 + lr)) * Hn + h0 + hc;
        g_thi[o] = hi;
        g_tlo[o] = __float2bfloat16(x - __bfloat162float(hi));
    }
}

// ---------------------------------------------------------------------------
// Kernel C: mma.sync bf16-split GEMM  (unchanged from R4 — passed)
// ---------------------------------------------------------------------------
#define BK 32
#define ROWB 80
#define MATB (128 * ROWB)
#define STAGEB (4 * MATB)
#define GEMM_SMEM (2 * STAGEB)

__global__ void __launch_bounds__(256, 1)
gemm_mma_kernel(const float* __restrict__ bias, float* __restrict__ out) {
    extern __shared__ __align__(16) char smem_raw[];
    const uint32_t buf = smem_u32(smem_raw);

    const int tid  = threadIdx.x;
    const int wid  = tid >> 5;
    const int lane = tid & 31;
    const int wm   = wid & 3;
    const int wn   = wid >> 2;
    const int m0   = blockIdx.x * 128;
    const int n0   = blockIdx.y * 128;
    const int b    = blockIdx.z;

    const __nv_bfloat16* Bhi = g_thi + (size_t)b * Ln * Hn;
    const __nv_bfloat16* Blo = g_tlo + (size_t)b * Ln * Hn;

    auto load_chunk = [&](int c, int s) {
        const int k0 = c * BK;
        const uint32_t sb = buf + s * STAGEB;
        #pragma unroll
        for (int j = 0; j < 2; j++) {
            const int i   = tid + j * 256;
            const int row = i >> 2;
            const int cc  = i & 3;
            const uint32_t so = row * ROWB + cc * 16;
            const size_t ga = (size_t)(m0 + row) * Hn + k0 + cc * 8;
            const size_t gb = (size_t)(n0 + row) * Hn + k0 + cc * 8;
            cp16(sb + 0 * MATB + so, g_Whi + ga);
            cp16(sb + 1 * MATB + so, g_Wlo + ga);
            cp16(sb + 2 * MATB + so, Bhi + gb);
            cp16(sb + 3 * MATB + so, Blo + gb);
        }
        CP_COMMIT();
    };

    float acc[2][8][4];
    #pragma unroll
    for (int i = 0; i < 2; i++)
        #pragma unroll
        for (int j = 0; j < 8; j++)
            #pragma unroll
            for (int q = 0; q < 4; q++) acc[i][j][q] = 0.0f;

    load_chunk(0, 0);

    const int NCH = Hn / BK;
    for (int c = 0; c < NCH; c++) {
        const int s = c & 1;
        if (c + 1 < NCH) {
            load_chunk(c + 1, s ^ 1);
            asm volatile("cp.async.wait_group 1;" ::: "memory");
        } else {
            asm volatile("cp.async.wait_group 0;" ::: "memory");
        }
        __syncthreads();

        const uint32_t aHi = buf + s * STAGEB;
        const uint32_t aLo = aHi + MATB;
        const uint32_t bHi = aHi + 2 * MATB;
        const uint32_t bLo = aHi + 3 * MATB;

        #pragma unroll
        for (int kk = 0; kk < BK; kk += 16) {
            uint32_t ah[2][4], al[2][4], bh[4][4], bl[4][4];
            #pragma unroll
            for (int mi = 0; mi < 2; mi++) {
                const int row = wm * 32 + mi * 16 + (lane & 15);
                const uint32_t off = row * ROWB + kk * 2 + ((lane >> 4) & 1) * 16;
                ldsm4(ah[mi], aHi + off);
                ldsm4(al[mi], aLo + off);
            }
            #pragma unroll
            for (int ng = 0; ng < 4; ng++) {
                const int row = wn * 64 + ng * 16 + (lane & 7) + ((lane >> 4) & 1) * 8;
                const uint32_t off = row * ROWB + kk * 2 + ((lane >> 3) & 1) * 16;
                ldsm4(bh[ng], bHi + off);
                ldsm4(bl[ng], bLo + off);
            }
            #pragma unroll
            for (int mi = 0; mi < 2; mi++)
                #pragma unroll
                for (int ng = 0; ng < 4; ng++)
                    #pragma unroll
                    for (int hf = 0; hf < 2; hf++) {
                        float* cc = acc[mi][ng * 2 + hf];
                        mma16816(cc, ah[mi], &bh[ng][hf * 2]);
                        mma16816(cc, ah[mi], &bl[ng][hf * 2]);
                        mma16816(cc, al[mi], &bh[ng][hf * 2]);
                    }
        }
        __syncthreads();
    }

    const int g  = lane >> 2;
    const int tg = lane & 3;
    #pragma unroll
    for (int mi = 0; mi < 2; mi++) {
        const int o0 = m0 + wm * 32 + mi * 16 + g;
        const float bv0 = bias[o0];
        const float bv1 = bias[o0 + 8];
        float* r0 = out + ((size_t)(b * Hn + o0)) * Ln + n0 + wn * 64;
        float* r1 = out + ((size_t)(b * Hn + o0 + 8)) * Ln + n0 + wn * 64;
        #pragma unroll
        for (int nf = 0; nf < 8; nf++) {
            const int col = nf * 8 + tg * 2;
            *(float2*)&r0[col] = make_float2(acc[mi][nf][0] + bv0, acc[mi][nf][1] + bv0);
            *(float2*)&r1[col] = make_float2(acc[mi][nf][2] + bv1, acc[mi][nf][3] + bv1);
        }
    }
}

// ---------------------------------------------------------------------------
extern "C" void kernel_launch(void* const* d_in, const int* in_sizes, int n_in,
                              void* d_out, int out_size) {
    const float* u    = (const float*)d_in[0];
    const float* k0   = (const float*)d_in[1];
    const float* k1   = (const float*)d_in[2];
    const float* k2   = (const float*)d_in[3];
    const float* k3   = (const float*)d_in[4];
    const float* D    = (const float*)d_in[5];
    const float* Wm   = (const float*)d_in[6];
    const float* bias = (const float*)d_in[7];
    float* out = (float*)d_out;

    cudaFuncSetAttribute(gemm_mma_kernel,
                         cudaFuncAttributeMaxDynamicSharedMemorySize, GEMM_SMEM);

    build_filter_kernel<<<Hn, 512>>>(k0, k1, k2, k3);

    dim3 gconv(Ln / 2048, Hn, Bn);
    fir_gelu_kernel<<<gconv, 256>>>(u, D);

    wsplit_kernel<<<(Hn * Hn) / 256, 256>>>(Wm);

    dim3 gt(Ln / 64, Hn / 64, Bn);
    tsplit_kernel<<<gt, 256>>>();

    dim3 gg(Hn / 128, Ln / 128, Bn);
    gemm_mma_kernel<<<gg, 256, GEMM_SMEM>>>(bias, out);
}

// round 9
// speedup vs baseline: 2.1099x; 1.0895x over previous
#include <cuda_runtime.h>
#include <cuda_bf16.h>
#include <math.h>
#include <stdint.h>

#define Hn   1024
#define Ln   8192
#define Bn   4
#define KDn  64
#define FLEN 512

// ---------------------------------------------------------------------------
// device scratch
// ---------------------------------------------------------------------------
__device__ float g_filt[Hn * FLEN];
__device__ __nv_bfloat16 g_Whi[Hn * Hn];
__device__ __nv_bfloat16 g_Wlo[Hn * Hn];
__device__ __nv_bfloat16 g_hi[(size_t)Bn * Hn * Ln];   // post-gelu, natural [b,h,l]
__device__ __nv_bfloat16 g_lo[(size_t)Bn * Hn * Ln];

// ---------------------------------------------------------------------------
// helpers
// ---------------------------------------------------------------------------
__device__ __forceinline__ uint32_t smem_u32(const void* p) {
    uint32_t a;
    asm("{ .reg .u64 t; cvta.to.shared.u64 t, %1; cvt.u32.u64 %0, t; }"
        : "=r"(a) : "l"(p));
    return a;
}
__device__ __forceinline__ void cp16(uint32_t dst, const void* src) {
    asm volatile("cp.async.cg.shared.global [%0], [%1], 16;" :: "r"(dst), "l"(src));
}
#define CP_COMMIT() asm volatile("cp.async.commit_group;" ::: "memory")

__device__ __forceinline__ void ldsm4(uint32_t* r, uint32_t addr) {
    asm volatile("ldmatrix.sync.aligned.m8n8.x4.shared.b16 {%0,%1,%2,%3}, [%4];"
                 : "=r"(r[0]), "=r"(r[1]), "=r"(r[2]), "=r"(r[3]) : "r"(addr));
}
__device__ __forceinline__ void ldsm4t(uint32_t* r, uint32_t addr) {
    asm volatile("ldmatrix.sync.aligned.m8n8.x4.trans.shared.b16 {%0,%1,%2,%3}, [%4];"
                 : "=r"(r[0]), "=r"(r[1]), "=r"(r[2]), "=r"(r[3]) : "r"(addr));
}
__device__ __forceinline__ void mma16816(float* c, const uint32_t* a, const uint32_t* b) {
    asm volatile("mma.sync.aligned.m16n8k16.row.col.f32.bf16.bf16.f32 "
                 "{%0,%1,%2,%3}, {%4,%5,%6,%7}, {%8,%9}, {%0,%1,%2,%3};"
                 : "+f"(c[0]), "+f"(c[1]), "+f"(c[2]), "+f"(c[3])
                 : "r"(a[0]), "r"(a[1]), "r"(a[2]), "r"(a[3]), "r"(b[0]), "r"(b[1]));
}

// packed f32x2
__device__ __forceinline__ uint64_t pack2(float lo, float hi) {
    uint64_t r;
    asm("mov.b64 %0, {%1, %2};" : "=l"(r) : "f"(lo), "f"(hi));
    return r;
}
__device__ __forceinline__ uint64_t ffma2(uint64_t a, uint64_t b, uint64_t c) {
    uint64_t r;
    asm("fma.rn.f32x2 %0, %1, %2, %3;" : "=l"(r) : "l"(a), "l"(b), "l"(c));
    return r;
}
__device__ __forceinline__ float2 unpack2(uint64_t p) {
    float2 v;
    asm("mov.b64 {%0, %1}, %2;" : "=f"(v.x), "=f"(v.y) : "l"(p));
    return v;
}

// ---------------------------------------------------------------------------
// Kernel A: build the 512-tap filter per head, L2-normalize.
// ---------------------------------------------------------------------------
__global__ void build_filter_kernel(const float* __restrict__ k0,
                                    const float* __restrict__ k1,
                                    const float* __restrict__ k2,
                                    const float* __restrict__ k3) {
    const int h = blockIdx.x;
    const int t = threadIdx.x;  // 0..511

    float v = 0.0f;
    if (t < 64) v += 8.0f * k0[h * KDn + t];
    const float* ks[3] = {k1, k2, k3};
    #pragma unroll
    for (int i = 1; i < 4; i++) {
        const int len = KDn << i;
        if (t < len) {
            const float scale = (float)(1 << i);
            float coord = ((float)t + 0.5f) / scale - 0.5f;
            coord = fminf(fmaxf(coord, 0.0f), 63.0f);
            int lo = (int)floorf(coord);
            if (lo > 63) lo = 63;
            int hi = lo + 1; if (hi > 63) hi = 63;
            const float w = coord - (float)lo;
            const float* kk = ks[i - 1];
            const float val = kk[h * KDn + lo] * (1.0f - w) + kk[h * KDn + hi] * w;
            v += val * (float)(1 << (3 - i));
        }
    }
    __shared__ float red[512];
    red[t] = v * v;
    __syncthreads();
    for (int s = 256; s > 0; s >>= 1) {
        if (t < s) red[t] += red[t + s];
        __syncthreads();
    }
    g_filt[h * FLEN + t] = v / sqrtf(red[0]);
}

// ---------------------------------------------------------------------------
// Kernel B: causal 512-tap FIR + D*u + exact GELU -> bf16 hi/lo (natural layout)
// f32x2-packed inner loop, sliding 16-value window.
// ---------------------------------------------------------------------------
struct Half8 {
    float   x[8];
    uint64_t e[4];
    uint64_t o[3];
};

__device__ __forceinline__ void load_half(Half8& h, const float* p) {
    *(float4*)&h.x[0] = *(const float4*)p;
    *(float4*)&h.x[4] = *(const float4*)(p + 4);
    h.e[0] = pack2(h.x[0], h.x[1]);
    h.e[1] = pack2(h.x[2], h.x[3]);
    h.e[2] = pack2(h.x[4], h.x[5]);
    h.e[3] = pack2(h.x[6], h.x[7]);
    h.o[0] = pack2(h.x[1], h.x[2]);
    h.o[1] = pack2(h.x[3], h.x[4]);
    h.o[2] = pack2(h.x[5], h.x[6]);
}

__device__ __forceinline__ void fir_step(uint64_t accP[4],
                                         const Half8& lo, const Half8& hi,
                                         const float* f) {
    const uint64_t cross = pack2(lo.x[7], hi.x[0]);
    float4 fa = *(const float4*)&f[0];
    float4 fb = *(const float4*)&f[4];
    const float fs[8] = {fa.x, fa.y, fa.z, fa.w, fb.x, fb.y, fb.z, fb.w};
    #pragma unroll
    for (int d = 0; d < 8; d++) {
        const uint64_t fd = pack2(fs[d], fs[d]);
        #pragma unroll
        for (int q = 0; q < 4; q++) {
            const int st = 8 + 2 * q - d;
            uint64_t xv;
            if ((d & 1) == 0) {
                const int i = st >> 1;
                xv = (i < 4) ? lo.e[i] : hi.e[i - 4];
            } else {
                const int j = (st - 1) >> 1;
                xv = (j < 3) ? lo.o[j] : (j == 3 ? cross : hi.o[j - 4]);
            }
            accP[q] = ffma2(fd, xv, accP[q]);
        }
    }
}

__global__ void __launch_bounds__(256) fir_gelu_kernel(const float* __restrict__ u,
                                                       const float* __restrict__ D) {
    const int chunk = blockIdx.x;
    const int h     = blockIdx.y;
    const int b     = blockIdx.z;
    const int tid   = threadIdx.x;

    __shared__ __align__(16) float s_u[FLEN + 2048];
    __shared__ __align__(16) float s_f[FLEN];

    const int l0 = chunk * 2048;
    const float* up = u + ((size_t)(b * Hn + h)) * Ln;

    for (int i = tid; i < FLEN + 2048; i += 256) {
        const int gl = l0 - FLEN + i;
        s_u[i] = (gl >= 0) ? up[gl] : 0.0f;
    }
    for (int i = tid; i < FLEN; i += 256) s_f[i] = g_filt[h * FLEN + i];
    __syncthreads();

    const int base = FLEN + tid * 8;

    uint64_t accP[4];
    #pragma unroll
    for (int q = 0; q < 4; q++) accP[q] = pack2(0.0f, 0.0f);

    Half8 A, B;
    load_half(B, &s_u[base]);
    #pragma unroll 4
    for (int t0 = 0; t0 < FLEN; t0 += 16) {
        load_half(A, &s_u[base - t0 - 8]);
        fir_step(accP, A, B, &s_f[t0]);
        load_half(B, &s_u[base - t0 - 16]);
        fir_step(accP, B, A, &s_f[t0 + 8]);
    }

    const float d = D[h];
    __nv_bfloat16 rh[8], rl[8];
    #pragma unroll
    for (int q = 0; q < 4; q++) {
        const float2 a = unpack2(accP[q]);
        const float v0 = a.x + d * s_u[base + 2 * q];
        const float v1 = a.y + d * s_u[base + 2 * q + 1];
        const float g0 = 0.5f * v0 * (1.0f + erff(v0 * 0.70710678118654752f));
        const float g1 = 0.5f * v1 * (1.0f + erff(v1 * 0.70710678118654752f));
        rh[2 * q]     = __float2bfloat16(g0);
        rl[2 * q]     = __float2bfloat16(g0 - __bfloat162float(rh[2 * q]));
        rh[2 * q + 1] = __float2bfloat16(g1);
        rl[2 * q + 1] = __float2bfloat16(g1 - __bfloat162float(rh[2 * q + 1]));
    }
    const size_t o = ((size_t)(b * Hn + h)) * Ln + l0 + tid * 8;
    *(uint4*)&g_hi[o] = *(uint4*)rh;
    *(uint4*)&g_lo[o] = *(uint4*)rl;
}

// ---------------------------------------------------------------------------
// Kernel W: split W into bf16 hi/lo
// ---------------------------------------------------------------------------
__global__ void wsplit_kernel(const float* __restrict__ W) {
    const int i = blockIdx.x * 256 + threadIdx.x;
    const float x = W[i];
    const __nv_bfloat16 h = __float2bfloat16(x);
    g_Whi[i] = h;
    g_Wlo[i] = __float2bfloat16(x - __bfloat162float(h));
}

// ---------------------------------------------------------------------------
// Kernel C: mma.sync bf16-split GEMM, natural-layout B via ldmatrix.trans
// out[b,o,l] = sum_h W[o,h] * g[b,h,l] + bias[o]
// CTA 128(M=o) x 128(N=l), BK=32 (K=h), 3-stage cp.async pipeline.
// A smem: [m=128][k=32] pitch 80B (non-trans ldmatrix).
// B smem: [k=32][n=128] pitch 272B (trans ldmatrix, conflict-free: bank step 4).
// ---------------------------------------------------------------------------
#define BK 32
#define AROW 80
#define BROW 272
#define AMAT (128 * AROW)             // 10240
#define BMAT (BK * BROW)              // 8704
#define STAGEB (2 * AMAT + 2 * BMAT)  // 37888
#define NSTAGE 3
#define GEMM_SMEM (NSTAGE * STAGEB)   // 113664

__global__ void __launch_bounds__(256, 1)
gemm_mma_kernel(const float* __restrict__ bias, float* __restrict__ out) {
    extern __shared__ __align__(16) char smem_raw[];
    const uint32_t buf = smem_u32(smem_raw);

    const int tid  = threadIdx.x;
    const int wid  = tid >> 5;
    const int lane = tid & 31;
    const int wm   = wid & 3;          // m sub-tile 0..3 (x32)
    const int wn   = wid >> 2;         // n sub-tile 0..1 (x64)
    const int m0   = blockIdx.x * 128;
    const int n0   = blockIdx.y * 128;
    const int b    = blockIdx.z;

    const __nv_bfloat16* Bhi = g_hi + (size_t)b * Hn * Ln;
    const __nv_bfloat16* Blo = g_lo + (size_t)b * Hn * Ln;

    auto load_chunk = [&](int c, int s) {
        const int k0 = c * BK;
        const uint32_t sb = buf + s * STAGEB;
        // A: W hi/lo, [m=128][k=32]
        for (int i = tid; i < 512; i += 256) {
            const int row = i >> 2;
            const int cc  = i & 3;
            const uint32_t so = row * AROW + cc * 16;
            const size_t ga = (size_t)(m0 + row) * Hn + k0 + cc * 8;
            cp16(sb + 0 * AMAT + so, g_Whi + ga);
            cp16(sb + 1 * AMAT + so, g_Wlo + ga);
        }
        // B: g hi/lo, [k=32][n=128] natural layout
        for (int i = tid; i < 512; i += 256) {
            const int row = i >> 4;             // k row 0..31
            const int cc  = i & 15;             // 16B chunk 0..15
            const uint32_t so = row * BROW + cc * 16;
            const size_t gb = (size_t)(k0 + row) * Ln + n0 + cc * 8;
            cp16(sb + 2 * AMAT + so, Bhi + gb);
            cp16(sb + 2 * AMAT + BMAT + so, Blo + gb);
        }
        CP_COMMIT();
    };

    float acc[2][8][4];
    #pragma unroll
    for (int i = 0; i < 2; i++)
        #pragma unroll
        for (int j = 0; j < 8; j++)
            #pragma unroll
            for (int q = 0; q < 4; q++) acc[i][j][q] = 0.0f;

    load_chunk(0, 0);
    load_chunk(1, 1);

    // B trans-ldmatrix lane addressing (within a k16 x n16 tile):
    const int grp   = lane >> 3;       // 0..3
    const int gr    = lane & 7;
    const int krowL = ((grp & 1) << 3) + gr;   // 0..15
    const int ncolL = (grp >> 1) << 3;         // 0 or 8

    const int NCH = Hn / BK;   // 32
    for (int c = 0; c < NCH; c++) {
        const int s = c % NSTAGE;
        if (c + 2 < NCH) load_chunk(c + 2, (c + 2) % NSTAGE);

        if (c + 2 < NCH)      asm volatile("cp.async.wait_group 2;" ::: "memory");
        else if (c + 1 < NCH) asm volatile("cp.async.wait_group 1;" ::: "memory");
        else                  asm volatile("cp.async.wait_group 0;" ::: "memory");
        __syncthreads();

        const uint32_t aHi = buf + s * STAGEB;
        const uint32_t aLo = aHi + AMAT;
        const uint32_t bHi = aHi + 2 * AMAT;
        const uint32_t bLo = bHi + BMAT;

        #pragma unroll
        for (int kk = 0; kk < BK; kk += 16) {
            uint32_t ah[2][4], al[2][4], bh[4][4], bl[4][4];
            #pragma unroll
            for (int mi = 0; mi < 2; mi++) {
                const int row = wm * 32 + mi * 16 + (lane & 15);
                const uint32_t off = row * AROW + kk * 2 + ((lane >> 4) & 1) * 16;
                ldsm4(ah[mi], aHi + off);
                ldsm4(al[mi], aLo + off);
            }
            #pragma unroll
            for (int ng = 0; ng < 4; ng++) {
                const int nbase = wn * 64 + ng * 16;
                const uint32_t off = (kk + krowL) * BROW + (nbase + ncolL) * 2;
                ldsm4t(bh[ng], bHi + off);
                ldsm4t(bl[ng], bLo + off);
            }
            #pragma unroll
            for (int mi = 0; mi < 2; mi++)
                #pragma unroll
                for (int ng = 0; ng < 4; ng++)
                    #pragma unroll
                    for (int hf = 0; hf < 2; hf++) {
                        float* cc = acc[mi][ng * 2 + hf];
                        mma16816(cc, ah[mi], &bh[ng][hf * 2]);
                        mma16816(cc, ah[mi], &bl[ng][hf * 2]);
                        mma16816(cc, al[mi], &bh[ng][hf * 2]);
                    }
        }
        __syncthreads();
    }

    const int g  = lane >> 2;
    const int tg = lane & 3;
    #pragma unroll
    for (int mi = 0; mi < 2; mi++) {
        const int o0 = m0 + wm * 32 + mi * 16 + g;
        const float bv0 = bias[o0];
        const float bv1 = bias[o0 + 8];
        float* r0 = out + ((size_t)(b * Hn + o0)) * Ln + n0 + wn * 64;
        float* r1 = out + ((size_t)(b * Hn + o0 + 8)) * Ln + n0 + wn * 64;
        #pragma unroll
        for (int nf = 0; nf < 8; nf++) {
            const int col = nf * 8 + tg * 2;
            *(float2*)&r0[col] = make_float2(acc[mi][nf][0] + bv0, acc[mi][nf][1] + bv0);
            *(float2*)&r1[col] = make_float2(acc[mi][nf][2] + bv1, acc[mi][nf][3] + bv1);
        }
    }
}

// ---------------------------------------------------------------------------
extern "C" void kernel_launch(void* const* d_in, const int* in_sizes, int n_in,
                              void* d_out, int out_size) {
    const float* u    = (const float*)d_in[0];
    const float* k0   = (const float*)d_in[1];
    const float* k1   = (const float*)d_in[2];
    const float* k2   = (const float*)d_in[3];
    const float* k3   = (const float*)d_in[4];
    const float* D    = (const float*)d_in[5];
    const float* Wm   = (const float*)d_in[6];
    const float* bias = (const float*)d_in[7];
    float* out = (float*)d_out;

    cudaFuncSetAttribute(gemm_mma_kernel,
                         cudaFuncAttributeMaxDynamicSharedMemorySize, GEMM_SMEM);

    build_filter_kernel<<<Hn, 512>>>(k0, k1, k2, k3);

    dim3 gconv(Ln / 2048, Hn, Bn);
    fir_gelu_kernel<<<gconv, 256>>>(u, D);

    wsplit_kernel<<<(Hn * Hn) / 256, 256>>>(Wm);

    dim3 gg(Hn / 128, Ln / 128, Bn);   // m fastest -> B-tile L2 reuse
    gemm_mma_kernel<<<gg, 256, GEMM_SMEM>>>(bias, out);
}